// round 1
// baseline (speedup 1.0000x reference)
#include <cuda_runtime.h>

#define N_NODES 100000
#define HID 128

// Scratch node buffers (allocation-free rule: __device__ globals).
static __device__ float g_bufA[N_NODES * HID];
static __device__ float g_bufB[N_NODES * HID];
static __device__ int   g_is64;

// ---------------------------------------------------------------------------
// Zero the scatter accumulator (float4 stores, grid-stride).
// ---------------------------------------------------------------------------
__global__ void zero_kernel(float* __restrict__ buf, int n4) {
    int i = blockIdx.x * blockDim.x + threadIdx.x;
    int stride = gridDim.x * blockDim.x;
    float4 z = make_float4(0.f, 0.f, 0.f, 0.f);
    for (; i < n4; i += stride) ((float4*)buf)[i] = z;
}

// ---------------------------------------------------------------------------
// Detect whether the index tensor is int64 or int32.
// int64 data with values < N_NODES: every odd 32-bit word is 0, even in range.
// int32 data: odd words are real (nonzero w.h.p.) indices -> detected.
// Deterministic: same inputs -> same flag.
// ---------------------------------------------------------------------------
__global__ void detect_kernel(const int* __restrict__ idx32) {
    if (threadIdx.x == 0 && blockIdx.x == 0) {
        int is64 = 1;
        #pragma unroll 1
        for (int k = 0; k < 64; ++k) {
            int lo = idx32[2 * k];
            int hi = idx32[2 * k + 1];
            if (hi != 0 || lo < 0 || lo >= N_NODES) { is64 = 0; break; }
        }
        g_is64 = is64;
    }
}

// ---------------------------------------------------------------------------
// Edge stage: gated[e,h] = (sum_r rbf[e,r] * W_rbf[h,r]) * x[e,h]
// scatter-add into acc[node[e], h].  One warp per edge; lane handles 4 h's.
// Scatter via red.global.add.v4.f32 (16B L2 atomics, accumulator L2-resident).
// ---------------------------------------------------------------------------
__global__ __launch_bounds__(256) void edge_kernel(
    const float* __restrict__ x,
    const float* __restrict__ rbf,
    const void*  __restrict__ idxp,
    const float* __restrict__ W_rbf,
    float* __restrict__ acc,
    int E)
{
    __shared__ float ws[6][HID];   // W_rbf transposed: ws[r][h]
    const int tid = threadIdx.x;
    for (int t = tid; t < 6 * HID; t += blockDim.x)
        ws[t % 6][t / 6] = W_rbf[t];
    __syncthreads();

    const int lane = tid & 31;
    const int warp = tid >> 5;
    const int wpb  = blockDim.x >> 5;
    const int h0   = lane * 4;

    // Hoist the per-lane W_rbf slice out of the edge loop (24 regs).
    float4 w[6];
    #pragma unroll
    for (int r = 0; r < 6; ++r) w[r] = *(const float4*)&ws[r][h0];

    const int is64 = g_is64;
    const long long* i64 = (const long long*)idxp;
    const int*       i32 = (const int*)idxp;

    for (int e = blockIdx.x * wpb + warp; e < E; e += gridDim.x * wpb) {
        long long node = is64 ? i64[e] : (long long)i32[e];
        const float2* rp = (const float2*)(rbf + (size_t)e * 6);
        float2 r01 = rp[0], r23 = rp[1], r45 = rp[2];

        float4 p;
        p.x = w[0].x * r01.x; p.y = w[0].y * r01.x;
        p.z = w[0].z * r01.x; p.w = w[0].w * r01.x;
        #define ACCR(RV, RI) \
            p.x = fmaf(RV, w[RI].x, p.x); p.y = fmaf(RV, w[RI].y, p.y); \
            p.z = fmaf(RV, w[RI].z, p.z); p.w = fmaf(RV, w[RI].w, p.w);
        ACCR(r01.y, 1) ACCR(r23.x, 2) ACCR(r23.y, 3) ACCR(r45.x, 4) ACCR(r45.y, 5)
        #undef ACCR

        float4 xv = *(const float4*)(x + (size_t)e * HID + h0);
        p.x *= xv.x; p.y *= xv.y; p.z *= xv.z; p.w *= xv.w;

        float* dst = acc + node * HID + h0;   // 16B aligned
        asm volatile("red.global.add.v4.f32 [%0], {%1, %2, %3, %4};"
                     :: "l"(dst), "f"(p.x), "f"(p.y), "f"(p.z), "f"(p.w)
                     : "memory");
    }
}

// ---------------------------------------------------------------------------
// Node MLP layer: out[n, j] = act( sum_k in[n,k] * W[j,k] + b[j] )
// Classic SIMT sgemm: BM=128, BN=128 (full width), BK=16; 256 threads,
// 8x8 microtile per thread. Both in and W are K-contiguous -> coalesced.
// ---------------------------------------------------------------------------
__global__ __launch_bounds__(256) void mlp_gemm_kernel(
    const float* __restrict__ in,
    const float* __restrict__ W,
    const float* __restrict__ bias,
    float* __restrict__ out,
    int N, int apply_silu)
{
    __shared__ float As[16][128];   // As[k][m]
    __shared__ float Bs[16][128];   // Bs[k][n]

    const int tid  = threadIdx.x;
    const int tx   = tid & 15;      // n-group
    const int ty   = tid >> 4;      // m-group
    const int row0 = blockIdx.x * 128;

    const int lrow = tid >> 2;           // 0..63
    const int lc4  = (tid & 3) * 4;      // 0,4,8,12

    float acc[8][8];
    #pragma unroll
    for (int i = 0; i < 8; ++i)
        #pragma unroll
        for (int j = 0; j < 8; ++j) acc[i][j] = 0.f;

    for (int kt = 0; kt < 128; kt += 16) {
        #pragma unroll
        for (int l = 0; l < 2; ++l) {
            int row = lrow + l * 64;
            int gr  = row0 + row;
            float4 av = make_float4(0.f, 0.f, 0.f, 0.f);
            if (gr < N) av = *(const float4*)(in + (size_t)gr * 128 + kt + lc4);
            As[lc4 + 0][row] = av.x; As[lc4 + 1][row] = av.y;
            As[lc4 + 2][row] = av.z; As[lc4 + 3][row] = av.w;
            float4 bv = *(const float4*)(W + (size_t)row * 128 + kt + lc4);
            Bs[lc4 + 0][row] = bv.x; Bs[lc4 + 1][row] = bv.y;
            Bs[lc4 + 2][row] = bv.z; Bs[lc4 + 3][row] = bv.w;
        }
        __syncthreads();

        #pragma unroll
        for (int k = 0; k < 16; ++k) {
            float4 a0 = *(const float4*)&As[k][ty * 8];
            float4 a1 = *(const float4*)&As[k][ty * 8 + 4];
            float4 b0 = *(const float4*)&Bs[k][tx * 8];
            float4 b1 = *(const float4*)&Bs[k][tx * 8 + 4];
            float a[8] = {a0.x, a0.y, a0.z, a0.w, a1.x, a1.y, a1.z, a1.w};
            float b[8] = {b0.x, b0.y, b0.z, b0.w, b1.x, b1.y, b1.z, b1.w};
            #pragma unroll
            for (int i = 0; i < 8; ++i)
                #pragma unroll
                for (int j = 0; j < 8; ++j)
                    acc[i][j] = fmaf(a[i], b[j], acc[i][j]);
        }
        __syncthreads();
    }

    float bb[8];
    #pragma unroll
    for (int j = 0; j < 8; ++j) bb[j] = bias ? bias[tx * 8 + j] : 0.f;

    #pragma unroll
    for (int i = 0; i < 8; ++i) {
        int gr = row0 + ty * 8 + i;
        if (gr < N) {
            float v[8];
            #pragma unroll
            for (int j = 0; j < 8; ++j) {
                float s = acc[i][j] + bb[j];
                if (apply_silu) s = s / (1.f + __expf(-s));
                v[j] = s;
            }
            float* op = out + (size_t)gr * 128 + tx * 8;
            *(float4*)op       = make_float4(v[0], v[1], v[2], v[3]);
            *(float4*)(op + 4) = make_float4(v[4], v[5], v[6], v[7]);
        }
    }
}

// ---------------------------------------------------------------------------
// Launch: zero -> detect -> edge scatter -> 4 GEMM layers (ping-pong in L2).
// All on the default stream; graph-capturable, allocation-free.
// ---------------------------------------------------------------------------
extern "C" void kernel_launch(void* const* d_in, const int* in_sizes, int n_in,
                              void* d_out, int out_size) {
    const float* x     = (const float*)d_in[0];
    const float* rbf   = (const float*)d_in[1];
    const void*  idx   = d_in[2];
    const float* W_rbf = (const float*)d_in[3];
    const float* W1    = (const float*)d_in[4];
    const float* b1    = (const float*)d_in[5];
    const float* W2    = (const float*)d_in[6];
    const float* b2    = (const float*)d_in[7];
    const float* W3    = (const float*)d_in[8];
    const float* b3    = (const float*)d_in[9];
    const float* W_out = (const float*)d_in[10];
    float* out = (float*)d_out;

    const int E = in_sizes[0] / HID;

    float *bufA = nullptr, *bufB = nullptr;
    cudaGetSymbolAddress((void**)&bufA, g_bufA);
    cudaGetSymbolAddress((void**)&bufB, g_bufB);

    zero_kernel<<<2048, 256>>>(bufA, N_NODES * HID / 4);
    detect_kernel<<<1, 32>>>((const int*)idx);
    edge_kernel<<<8192, 256>>>(x, rbf, idx, W_rbf, bufA, E);

    const int gtiles = (N_NODES + 127) / 128;
    mlp_gemm_kernel<<<gtiles, 256>>>(bufA, W1, b1, bufB, N_NODES, 1);
    mlp_gemm_kernel<<<gtiles, 256>>>(bufB, W2, b2, bufA, N_NODES, 1);
    mlp_gemm_kernel<<<gtiles, 256>>>(bufA, W3, b3, bufB, N_NODES, 1);
    mlp_gemm_kernel<<<gtiles, 256>>>(bufB, W_out, nullptr, out, N_NODES, 0);
}

// round 5
// speedup vs baseline: 1.3364x; 1.3364x over previous
#include <cuda_runtime.h>
#include <cuda_bf16.h>
#include <cstdint>

#define N_NODES 100000
#define HID 128

// Scratch node accumulator (allocation-free rule: __device__ global).
static __device__ float g_bufA[N_NODES * HID];
static __device__ int   g_is64;

// ---------------------------------------------------------------------------
// Helpers
// ---------------------------------------------------------------------------
__device__ __forceinline__ uint32_t smem_u32(const void* p) {
    uint32_t a;
    asm("{ .reg .u64 t; cvta.to.shared.u64 t, %1; cvt.u32.u64 %0, t; }"
        : "=r"(a) : "l"(p));
    return a;
}

__device__ __forceinline__ void hilo2(float x, float y, uint32_t& h, uint32_t& l) {
    __nv_bfloat162 bh = __floats2bfloat162_rn(x, y);
    float rx = x - __bfloat162float(bh.x);
    float ry = y - __bfloat162float(bh.y);
    __nv_bfloat162 bl = __floats2bfloat162_rn(rx, ry);
    h = *(uint32_t*)&bh;
    l = *(uint32_t*)&bl;
}

#define LDSM_X4(r0, r1, r2, r3, a)                                            \
    asm volatile("ldmatrix.sync.aligned.m8n8.x4.shared.b16 {%0,%1,%2,%3},[%4];" \
                 : "=r"(r0), "=r"(r1), "=r"(r2), "=r"(r3) : "r"(a))
#define LDSM_X2(r0, r1, a)                                                    \
    asm volatile("ldmatrix.sync.aligned.m8n8.x2.shared.b16 {%0,%1},[%2];"     \
                 : "=r"(r0), "=r"(r1) : "r"(a))

#define MMA_BF16(d, a0, a1, a2, a3, b0, b1)                                   \
    asm volatile(                                                             \
        "mma.sync.aligned.m16n8k16.row.col.f32.bf16.bf16.f32 "                \
        "{%0,%1,%2,%3}, {%4,%5,%6,%7}, {%8,%9}, {%0,%1,%2,%3};"               \
        : "+f"((d)[0]), "+f"((d)[1]), "+f"((d)[2]), "+f"((d)[3])              \
        : "r"(a0), "r"(a1), "r"(a2), "r"(a3), "r"(b0), "r"(b1))

// ---------------------------------------------------------------------------
// Zero / detect
// ---------------------------------------------------------------------------
__global__ void zero_kernel(float* __restrict__ buf, int n4) {
    int i = blockIdx.x * blockDim.x + threadIdx.x;
    int stride = gridDim.x * blockDim.x;
    float4 z = make_float4(0.f, 0.f, 0.f, 0.f);
    for (; i < n4; i += stride) ((float4*)buf)[i] = z;
}

__global__ void detect_kernel(const int* __restrict__ idx32) {
    if (threadIdx.x == 0 && blockIdx.x == 0) {
        int is64 = 1;
        #pragma unroll 1
        for (int k = 0; k < 64; ++k) {
            int lo = idx32[2 * k];
            int hi = idx32[2 * k + 1];
            if (hi != 0 || lo < 0 || lo >= N_NODES) { is64 = 0; break; }
        }
        g_is64 = is64;
    }
}

// ---------------------------------------------------------------------------
// Edge stage: warp/edge, red.global.add.v4.f32 scatter.
// ---------------------------------------------------------------------------
__global__ __launch_bounds__(256) void edge_kernel(
    const float* __restrict__ x,
    const float* __restrict__ rbf,
    const void*  __restrict__ idxp,
    const float* __restrict__ W_rbf,
    float* __restrict__ acc,
    int E)
{
    __shared__ float ws[6][HID];
    const int tid = threadIdx.x;
    for (int t = tid; t < 6 * HID; t += blockDim.x)
        ws[t % 6][t / 6] = W_rbf[t];
    __syncthreads();

    const int lane = tid & 31;
    const int warp = tid >> 5;
    const int wpb  = blockDim.x >> 5;
    const int h0   = lane * 4;

    float4 w[6];
    #pragma unroll
    for (int r = 0; r < 6; ++r) w[r] = *(const float4*)&ws[r][h0];

    const int is64 = g_is64;
    const long long* i64 = (const long long*)idxp;
    const int*       i32 = (const int*)idxp;

    for (int e = blockIdx.x * wpb + warp; e < E; e += gridDim.x * wpb) {
        long long node = is64 ? i64[e] : (long long)i32[e];
        const float2* rp = (const float2*)(rbf + (size_t)e * 6);
        float2 r01 = rp[0], r23 = rp[1], r45 = rp[2];

        float4 p;
        p.x = w[0].x * r01.x; p.y = w[0].y * r01.x;
        p.z = w[0].z * r01.x; p.w = w[0].w * r01.x;
        #define ACCR(RV, RI) \
            p.x = fmaf(RV, w[RI].x, p.x); p.y = fmaf(RV, w[RI].y, p.y); \
            p.z = fmaf(RV, w[RI].z, p.z); p.w = fmaf(RV, w[RI].w, p.w);
        ACCR(r01.y, 1) ACCR(r23.x, 2) ACCR(r23.y, 3) ACCR(r45.x, 4) ACCR(r45.y, 5)
        #undef ACCR

        float4 xv = *(const float4*)(x + (size_t)e * HID + h0);
        p.x *= xv.x; p.y *= xv.y; p.z *= xv.z; p.w *= xv.w;

        float* dst = acc + node * HID + h0;
        asm volatile("red.global.add.v4.f32 [%0], {%1, %2, %3, %4};"
                     :: "l"(dst), "f"(p.x), "f"(p.y), "f"(p.z), "f"(p.w)
                     : "memory");
    }
}

// ---------------------------------------------------------------------------
// Fused 4-layer MLP on mma.sync (bf16 hi/lo compensated, fp32 accumulate).
// Tile: 256 rows x 128 cols per CTA; 16 warps, warp w owns rows [16w,16w+16).
// SMEM bf16 tiles, row stride 136 elems (272B, 16B-aligned rows).
// D = Ahi*Whi + Alo*Whi + Ahi*Wlo (3x mma.sync per k-step/n-tile).
// ---------------------------------------------------------------------------
#define ST       136
#define A_BYTES  (256 * ST * 2)          /* 69632  */
#define W_BYTES  (128 * ST * 2)          /* 34816  */
#define SM_A_HI  0
#define SM_A_LO  (A_BYTES)
#define SM_W_HI  (2 * A_BYTES)
#define SM_W_LO  (2 * A_BYTES + W_BYTES)
#define SMEM_TOT (2 * A_BYTES + 2 * W_BYTES)   /* 208896 */

// Convert one 128x128 fp32 weight matrix into W_hi/W_lo SMEM tiles.
__device__ __forceinline__ void convert_W(uint32_t sb, const float* __restrict__ W,
                                          int w, int L) {
    int r  = w * 8 + (L >> 2);
    int cb = (L & 3) * 4;
    #pragma unroll
    for (int g = 0; g < 8; ++g) {
        int c = cb + g * 16;
        float4 v = *(const float4*)(W + (size_t)r * 128 + c);
        uint32_t h0, l0, h1, l1;
        hilo2(v.x, v.y, h0, l0);
        hilo2(v.z, v.w, h1, l1);
        uint32_t off = (uint32_t)(r * ST + c) * 2;
        asm volatile("st.shared.v2.b32 [%0], {%1,%2};"
                     :: "r"(sb + SM_W_HI + off), "r"(h0), "r"(h1));
        asm volatile("st.shared.v2.b32 [%0], {%1,%2};"
                     :: "r"(sb + SM_W_LO + off), "r"(l0), "r"(l1));
    }
}

__global__ void __launch_bounds__(512, 1) mlp_fused_kernel(
    const float* __restrict__ in,
    const float* __restrict__ W1, const float* __restrict__ b1,
    const float* __restrict__ W2, const float* __restrict__ b2,
    const float* __restrict__ W3, const float* __restrict__ b3,
    const float* __restrict__ Wo,
    float* __restrict__ out)
{
    extern __shared__ char smem[];
    uint32_t sb = smem_u32(smem);
    const int tid  = threadIdx.x;
    const int w    = tid >> 5;
    const int L    = tid & 31;
    const int row0 = blockIdx.x * 256;

    // ---- Load A tile (256 rows of h), fp32 -> bf16 hi/lo, zero-pad OOB ----
    {
        int r  = w * 16 + (L >> 1);
        int gr = row0 + r;
        int cb = (L & 1) * 64;
        #pragma unroll
        for (int g = 0; g < 8; ++g) {
            int c = cb + g * 8;
            float v[8];
            if (gr < N_NODES) {
                float4 u0 = *(const float4*)(in + (size_t)gr * 128 + c);
                float4 u1 = *(const float4*)(in + (size_t)gr * 128 + c + 4);
                v[0]=u0.x; v[1]=u0.y; v[2]=u0.z; v[3]=u0.w;
                v[4]=u1.x; v[5]=u1.y; v[6]=u1.z; v[7]=u1.w;
            } else {
                #pragma unroll
                for (int i = 0; i < 8; ++i) v[i] = 0.f;
            }
            uint32_t h[4], l[4];
            #pragma unroll
            for (int i = 0; i < 4; ++i) hilo2(v[2*i], v[2*i+1], h[i], l[i]);
            uint32_t off = (uint32_t)(r * ST + c) * 2;
            asm volatile("st.shared.v4.b32 [%0], {%1,%2,%3,%4};"
                         :: "r"(sb + SM_A_HI + off),
                            "r"(h[0]), "r"(h[1]), "r"(h[2]), "r"(h[3]));
            asm volatile("st.shared.v4.b32 [%0], {%1,%2,%3,%4};"
                         :: "r"(sb + SM_A_LO + off),
                            "r"(l[0]), "r"(l[1]), "r"(l[2]), "r"(l[3]));
        }
    }
    convert_W(sb, W1, w, L);
    __syncthreads();

    const float* Wn[3] = {W2, W3, Wo};
    const float* Bp[3] = {b1, b2, b3};

    // A-fragment base address (row = 16w + L%16, col-block = (L/16)*8)
    const uint32_t aOff = (uint32_t)((w * 16 + (L & 15)) * ST + ((L >> 4) << 3)) * 2;
    const int lb = L & 15;
    const uint32_t bRowOff = (uint32_t)((lb & 7) * ST + ((lb >> 3) << 3)) * 2;

    #pragma unroll 1
    for (int Layer = 0; Layer < 4; ++Layer) {
        const float* bias = (Layer < 3) ? Bp[Layer] : nullptr;
        const int p2 = 2 * (L & 3);

        float acc[64];
        #pragma unroll
        for (int nt = 0; nt < 16; ++nt) {
            float b0 = 0.f, c1 = 0.f;
            if (bias) { b0 = bias[nt * 8 + p2]; c1 = bias[nt * 8 + p2 + 1]; }
            acc[nt*4 + 0] = b0; acc[nt*4 + 1] = c1;
            acc[nt*4 + 2] = b0; acc[nt*4 + 3] = c1;
        }

        #pragma unroll
        for (int k = 0; k < 128; k += 16) {
            uint32_t ah0, ah1, ah2, ah3, al0, al1, al2, al3;
            LDSM_X4(ah0, ah1, ah2, ah3, sb + SM_A_HI + aOff + k * 2);
            LDSM_X4(al0, al1, al2, al3, sb + SM_A_LO + aOff + k * 2);
            #pragma unroll
            for (int nt = 0; nt < 16; ++nt) {
                uint32_t bAddr = bRowOff + (uint32_t)(nt * 8 * ST + k) * 2;
                uint32_t bh0, bh1, bl0, bl1;
                LDSM_X2(bh0, bh1, sb + SM_W_HI + bAddr);
                LDSM_X2(bl0, bl1, sb + SM_W_LO + bAddr);
                MMA_BF16(acc + nt*4, ah0, ah1, ah2, ah3, bh0, bh1);
                MMA_BF16(acc + nt*4, al0, al1, al2, al3, bh0, bh1);
                MMA_BF16(acc + nt*4, ah0, ah1, ah2, ah3, bl0, bl1);
            }
        }

        const int r0 = w * 16 + (L >> 2);
        if (Layer < 3) {
            // silu + convert back into A hi/lo (own rows only; warp-exclusive
            // stripe, cross-warp visibility covered by the barriers below).
            #pragma unroll
            for (int nt = 0; nt < 16; ++nt) {
                int c = nt * 8 + p2;
                float s[4];
                #pragma unroll
                for (int j = 0; j < 4; ++j) {
                    float v = acc[nt*4 + j];
                    s[j] = v / (1.f + __expf(-v));
                }
                uint32_t h0, l0, h1, l1;
                hilo2(s[0], s[1], h0, l0);
                hilo2(s[2], s[3], h1, l1);
                uint32_t o0 = (uint32_t)(r0 * ST + c) * 2;
                uint32_t o1 = (uint32_t)((r0 + 8) * ST + c) * 2;
                asm volatile("st.shared.b32 [%0], %1;" :: "r"(sb + SM_A_HI + o0), "r"(h0));
                asm volatile("st.shared.b32 [%0], %1;" :: "r"(sb + SM_A_LO + o0), "r"(l0));
                asm volatile("st.shared.b32 [%0], %1;" :: "r"(sb + SM_A_HI + o1), "r"(h1));
                asm volatile("st.shared.b32 [%0], %1;" :: "r"(sb + SM_A_LO + o1), "r"(l1));
            }
            __syncthreads();                 // everyone done reading W_L
            convert_W(sb, Wn[Layer], w, L);  // stage W_{L+1}
            __syncthreads();
        } else {
            // final layer: fp32 out
            int gr0 = row0 + r0;
            int gr1 = gr0 + 8;
            #pragma unroll
            for (int nt = 0; nt < 16; ++nt) {
                int c = nt * 8 + p2;
                if (gr0 < N_NODES)
                    *(float2*)(out + (size_t)gr0 * 128 + c) =
                        make_float2(acc[nt*4 + 0], acc[nt*4 + 1]);
                if (gr1 < N_NODES)
                    *(float2*)(out + (size_t)gr1 * 128 + c) =
                        make_float2(acc[nt*4 + 2], acc[nt*4 + 3]);
            }
        }
    }
}

// ---------------------------------------------------------------------------
// Launch
// ---------------------------------------------------------------------------
extern "C" void kernel_launch(void* const* d_in, const int* in_sizes, int n_in,
                              void* d_out, int out_size) {
    const float* x     = (const float*)d_in[0];
    const float* rbf   = (const float*)d_in[1];
    const void*  idx   = d_in[2];
    const float* W_rbf = (const float*)d_in[3];
    const float* W1    = (const float*)d_in[4];
    const float* b1    = (const float*)d_in[5];
    const float* W2    = (const float*)d_in[6];
    const float* b2    = (const float*)d_in[7];
    const float* W3    = (const float*)d_in[8];
    const float* b3    = (const float*)d_in[9];
    const float* W_out = (const float*)d_in[10];
    float* out = (float*)d_out;

    const int E = in_sizes[0] / HID;

    float* bufA = nullptr;
    cudaGetSymbolAddress((void**)&bufA, g_bufA);

    cudaFuncSetAttribute(mlp_fused_kernel,
                         cudaFuncAttributeMaxDynamicSharedMemorySize, SMEM_TOT);

    zero_kernel<<<2048, 256>>>(bufA, N_NODES * HID / 4);
    detect_kernel<<<1, 32>>>((const int*)idx);
    edge_kernel<<<8192, 256>>>(x, rbf, idx, W_rbf, bufA, E);

    const int gtiles = (N_NODES + 255) / 256;
    mlp_fused_kernel<<<gtiles, 512, SMEM_TOT>>>(bufA, W1, b1, W2, b2, W3, b3,
                                                W_out, out);
}